// round 1
// baseline (speedup 1.0000x reference)
#include <cuda_runtime.h>
#include <math.h>

#define MASK  0x7FFFFu
#define P1    2654435761u
#define P2    805459861u

struct Params {
    float icell[16];   // res/2  (u = (x+1) * icell)
    float resm1[16];   // res-1 as float (clamp ceiling)
};

__device__ __forceinline__ unsigned long long pk2(float a, float b) {
    unsigned long long r;
    asm("mov.b64 %0, {%1, %2};" : "=l"(r) : "f"(a), "f"(b));
    return r;
}

// packed lerp: a + t*(b-a) on two f32 lanes (sm_100+ f32x2 ops)
__device__ __forceinline__ unsigned long long lerp2(unsigned long long a,
                                                    unsigned long long b,
                                                    unsigned long long t) {
    unsigned long long d, r;
    asm("sub.rn.f32x2 %0, %1, %2;" : "=l"(d) : "l"(b), "l"(a));
    asm("fma.rn.f32x2 %0, %1, %2, %3;" : "=l"(r) : "l"(t), "l"(d), "l"(a));
    return r;
}

__global__ __launch_bounds__(256) void hash_embed_kernel(
    const float* __restrict__ x,
    const unsigned long long* __restrict__ tbl,   // tables as (level<<19) float2 entries
    float* __restrict__ out,
    int npts,
    Params prm)
{
    unsigned p = blockIdx.x * 256u + threadIdx.x;
    if (p >= (unsigned)npts) return;

    float px = __ldg(x + 3u * p + 0);
    float py = __ldg(x + 3u * p + 1);
    float pz = __ldg(x + 3u * p + 2);

    float* outp = out + (unsigned long long)p * 32u;
    unsigned long long res[4];

#pragma unroll
    for (int l = 0; l < 16; l++) {
        const float ic  = prm.icell[l];
        const float rm1 = prm.resm1[l];

        // continuous grid coords u = (x+1)*res/2, bottom corner, fraction
        float ux = fmaf(px, ic, ic);
        float uy = fmaf(py, ic, ic);
        float uz = fmaf(pz, ic, ic);
        float fx = fminf(floorf(ux), rm1);
        float fy = fminf(floorf(uy), rm1);
        float fz = fminf(floorf(uz), rm1);
        float tx = ux - fx;
        float ty = uy - fy;
        float tz = uz - fz;

        unsigned ix0 = (unsigned)fx;
        unsigned iy0 = (unsigned)fy;
        unsigned iz0 = (unsigned)fz;
        unsigned ix1 = ix0 + 1u;
        unsigned hy0 = iy0 * P1;
        unsigned hy1 = hy0 + P1;
        unsigned hz0 = iz0 * P2;
        unsigned hz1 = hz0 + P2;

        const unsigned long long* tl = tbl + ((unsigned)l << 19);

        // 8 corner gathers (LDG.64 each, independent -> high MLP)
        unsigned long long e000 = __ldg(tl + ((ix0 ^ hy0 ^ hz0) & MASK));
        unsigned long long e100 = __ldg(tl + ((ix1 ^ hy0 ^ hz0) & MASK));
        unsigned long long e010 = __ldg(tl + ((ix0 ^ hy1 ^ hz0) & MASK));
        unsigned long long e110 = __ldg(tl + ((ix1 ^ hy1 ^ hz0) & MASK));
        unsigned long long e001 = __ldg(tl + ((ix0 ^ hy0 ^ hz1) & MASK));
        unsigned long long e101 = __ldg(tl + ((ix1 ^ hy0 ^ hz1) & MASK));
        unsigned long long e011 = __ldg(tl + ((ix0 ^ hy1 ^ hz1) & MASK));
        unsigned long long e111 = __ldg(tl + ((ix1 ^ hy1 ^ hz1) & MASK));

        unsigned long long t2x = pk2(tx, tx);
        unsigned long long t2y = pk2(ty, ty);
        unsigned long long t2z = pk2(tz, tz);

        // trilinear via packed lerp tree (both features per op)
        unsigned long long a0 = lerp2(e000, e100, t2x);
        unsigned long long a1 = lerp2(e010, e110, t2x);
        unsigned long long a2 = lerp2(e001, e101, t2x);
        unsigned long long a3 = lerp2(e011, e111, t2x);
        unsigned long long b0 = lerp2(a0, a1, t2y);
        unsigned long long b1 = lerp2(a2, a3, t2y);
        res[l & 3] = lerp2(b0, b1, t2z);

        if ((l & 3) == 3) {
            int g = l >> 2;
            ulonglong2 v0 = make_ulonglong2(res[0], res[1]);
            ulonglong2 v1 = make_ulonglong2(res[2], res[3]);
            *reinterpret_cast<ulonglong2*>(outp + g * 8 + 0) = v0;
            *reinterpret_cast<ulonglong2*>(outp + g * 8 + 4) = v1;
        }
    }
}

extern "C" void kernel_launch(void* const* d_in, const int* in_sizes, int n_in,
                              void* d_out, int out_size) {
    // inputs: x (BSZ*3 f32), tables (16*2^19*2 f32); detect order by size
    int xi = 0, ti = 1;
    if (n_in >= 2 && in_sizes[0] > in_sizes[1]) { xi = 1; ti = 0; }

    const float* x = (const float*)d_in[xi];
    const unsigned long long* tbl = (const unsigned long long*)d_in[ti];
    float* out = (float*)d_out;

    // Replicate numpy's resolution computation with the same host libm
    // (levels 3/6/9/12/15 sit on exact floor(16*2^(i/3)) boundaries).
    Params prm;
    double factor = exp((log(512.0) - log(16.0)) / 15.0);
    for (int i = 0; i < 16; i++) {
        double r = floor(16.0 * pow(factor, (double)i));
        prm.icell[i] = (float)(r * 0.5);
        prm.resm1[i] = (float)(r - 1.0);
    }

    int npts = in_sizes[xi] / 3;
    int blocks = (npts + 255) / 256;
    hash_embed_kernel<<<blocks, 256>>>(x, tbl, out, npts, prm);
}

// round 2
// speedup vs baseline: 1.0054x; 1.0054x over previous
#include <cuda_runtime.h>
#include <math.h>

#define MASK  0x7FFFFu
#define P1    2654435761u
#define P2    805459861u

struct Params {
    float icell[16];   // res/2  (u = (x+1) * icell)
    float resm1[16];   // res-1 as float (clamp ceiling)
};

typedef unsigned long long ull;

__device__ __forceinline__ ull pk2(float a, float b) {
    ull r;
    asm("mov.b64 %0, {%1, %2};" : "=l"(r) : "f"(a), "f"(b));
    return r;
}

// packed lerp: a + t*(b-a) on two f32 lanes (sm_100+ f32x2 ops)
__device__ __forceinline__ ull lerp2(ull a, ull b, ull t) {
    ull d, r;
    asm("sub.rn.f32x2 %0, %1, %2;" : "=l"(d) : "l"(b), "l"(a));
    asm("fma.rn.f32x2 %0, %1, %2, %3;" : "=l"(r) : "l"(t), "l"(d), "l"(a));
    return r;
}

__global__ __launch_bounds__(256) void hash_embed_kernel(
    const float* __restrict__ x,
    const ull* __restrict__ tbl,   // tables as (level<<19) float2 entries
    float* __restrict__ out,
    int npts,
    Params prm)
{
    unsigned p = blockIdx.x * 256u + threadIdx.x;
    if (p >= (unsigned)npts) return;

    float px = __ldg(x + 3u * p + 0);
    float py = __ldg(x + 3u * p + 1);
    float pz = __ldg(x + 3u * p + 2);

    float* outp = out + (ull)p * 32u;
    ull res[4];

#pragma unroll
    for (int l = 0; l < 16; l++) {
        const float ic  = prm.icell[l];
        const float rm1 = prm.resm1[l];

        // continuous grid coords u = (x+1)*res/2, bottom corner, fraction
        float ux = fmaf(px, ic, ic);
        float uy = fmaf(py, ic, ic);
        float uz = fmaf(pz, ic, ic);
        float fx = fminf(floorf(ux), rm1);
        float fy = fminf(floorf(uy), rm1);
        float fz = fminf(floorf(uz), rm1);
        float tx = ux - fx;
        float ty = uy - fy;
        float tz = uz - fz;

        unsigned ix0 = (unsigned)fx;
        unsigned iy0 = (unsigned)fy;
        unsigned iz0 = (unsigned)fz;
        unsigned hy0 = iy0 * P1;
        unsigned hy1 = hy0 + P1;
        unsigned hz0 = iz0 * P2;
        unsigned hz1 = hz0 + P2;

        // yz hash combos
        unsigned r00 = hy0 ^ hz0;
        unsigned r10 = hy1 ^ hz0;
        unsigned r01 = hy0 ^ hz1;
        unsigned r11 = hy1 ^ hz1;

        unsigned h00 = (ix0 ^ r00) & MASK;
        unsigned h10 = (ix0 ^ r10) & MASK;
        unsigned h01 = (ix0 ^ r01) & MASK;
        unsigned h11 = (ix0 ^ r11) & MASK;

        const ull* tl = tbl + ((unsigned)l << 19);
        const ulonglong2* tp = (const ulonglong2*)tl;

        // One 16B load per corner pair: entries {h&~1, h|1} = corners (ix0, ix0^1).
        // For even ix0, ix0^1 == ix0+1 -> both corners in one load.
        ulonglong2 q00 = __ldg(tp + (h00 >> 1));
        ulonglong2 q10 = __ldg(tp + (h10 >> 1));
        ulonglong2 q01 = __ldg(tp + (h01 >> 1));
        ulonglong2 q11 = __ldg(tp + (h11 >> 1));

        ull e000 = (h00 & 1) ? q00.y : q00.x;
        ull e010 = (h10 & 1) ? q10.y : q10.x;
        ull e001 = (h01 & 1) ? q01.y : q01.x;
        ull e011 = (h11 & 1) ? q11.y : q11.x;

        ull e100, e110, e101, e111;
        if (ix0 & 1) {
            // odd ix0: +x corner is ix0+1 (even), not ix0^1 -> separate loads
            unsigned ix1 = ix0 + 1u;
            e100 = __ldg(tl + ((ix1 ^ r00) & MASK));
            e110 = __ldg(tl + ((ix1 ^ r10) & MASK));
            e101 = __ldg(tl + ((ix1 ^ r01) & MASK));
            e111 = __ldg(tl + ((ix1 ^ r11) & MASK));
        } else {
            // even ix0: other half of the pair IS the +x corner
            e100 = (h00 & 1) ? q00.x : q00.y;
            e110 = (h10 & 1) ? q10.x : q10.y;
            e101 = (h01 & 1) ? q01.x : q01.y;
            e111 = (h11 & 1) ? q11.x : q11.y;
        }

        ull t2x = pk2(tx, tx);
        ull t2y = pk2(ty, ty);
        ull t2z = pk2(tz, tz);

        // trilinear via packed lerp tree (both features per op)
        ull a0 = lerp2(e000, e100, t2x);
        ull a1 = lerp2(e010, e110, t2x);
        ull a2 = lerp2(e001, e101, t2x);
        ull a3 = lerp2(e011, e111, t2x);
        ull b0 = lerp2(a0, a1, t2y);
        ull b1 = lerp2(a2, a3, t2y);
        res[l & 3] = lerp2(b0, b1, t2z);

        if ((l & 3) == 3) {
            int g = l >> 2;
            ulonglong2 v0 = make_ulonglong2(res[0], res[1]);
            ulonglong2 v1 = make_ulonglong2(res[2], res[3]);
            *reinterpret_cast<ulonglong2*>(outp + g * 8 + 0) = v0;
            *reinterpret_cast<ulonglong2*>(outp + g * 8 + 4) = v1;
        }
    }
}

extern "C" void kernel_launch(void* const* d_in, const int* in_sizes, int n_in,
                              void* d_out, int out_size) {
    // inputs: x (BSZ*3 f32), tables (16*2^19*2 f32); detect order by size
    int xi = 0, ti = 1;
    if (n_in >= 2 && in_sizes[0] > in_sizes[1]) { xi = 1; ti = 0; }

    const float* x = (const float*)d_in[xi];
    const ull* tbl = (const ull*)d_in[ti];
    float* out = (float*)d_out;

    // Replicate numpy's resolution computation with the same host libm
    // (levels 3/6/9/12/15 sit on exact floor(16*2^(i/3)) boundaries).
    Params prm;
    double factor = exp((log(512.0) - log(16.0)) / 15.0);
    for (int i = 0; i < 16; i++) {
        double r = floor(16.0 * pow(factor, (double)i));
        prm.icell[i] = (float)(r * 0.5);
        prm.resm1[i] = (float)(r - 1.0);
    }

    int npts = in_sizes[xi] / 3;
    int blocks = (npts + 255) / 256;
    hash_embed_kernel<<<blocks, 256>>>(x, tbl, out, npts, prm);
}